// round 6
// baseline (speedup 1.0000x reference)
#include <cuda_runtime.h>
#include <cuda_fp16.h>
#include <cstdint>
#include <math.h>

#define B_  1024
#define V_  50257
#define E_  128
#define NT_ 393          // ceil(V_/128)
#define VP_ (NT_ * 128)  // 50304 padded rows
#define GX_ 19           // n-split: 152 CTAs = 1 per SM

// ---- scratch (no allocations allowed) ----
__device__ int     g_idx[B_];
__device__ __half  g_yh[B_ * E_];
__device__ __half  g_negh[(size_t)VP_ * E_];      // padded half copy of NEGEMBEDM
__device__ float2  g_part2[(size_t)B_ * NT_ * 4]; // per-(row, tile, warp_n) partials
__device__ float   g_lse[B_];

__device__ __forceinline__ uint32_t smem_u32(const void* p) {
    uint32_t a;
    asm("{ .reg .u64 t; cvta.to.shared.u64 t, %1; cvt.u32.u64 %0, t; }"
        : "=r"(a) : "l"(p));
    return a;
}

// ---------------- K1: recover one-hot indices (bandwidth-bound scan) --------
__global__ void find_idx_kernel(const float4* __restrict__ xs4) {
    const long n4 = (long)B_ * V_ / 4;
    for (long i = blockIdx.x * (long)blockDim.x + threadIdx.x; i < n4;
         i += (long)gridDim.x * blockDim.x) {
        float4 v = xs4[i];
        if (v.x != 0.f || v.y != 0.f || v.z != 0.f || v.w != 0.f) {
            float vals[4] = {v.x, v.y, v.z, v.w};
            long base = i * 4;
#pragma unroll
            for (int j = 0; j < 4; j++) {
                if (vals[j] != 0.f) {
                    long p = base + j;
                    int  b = (int)(p / V_);
                    g_idx[b] = (int)(p - (long)b * V_);
                }
            }
        }
    }
}

// ---------------- K1b: convert NEGEMBEDM fp32 -> padded half ----------------
__global__ void conv_neg_kernel(const float4* __restrict__ neg4) {
    const long n8 = (long)VP_ * E_ / 8;   // 8 halves per iter
    for (long i = blockIdx.x * (long)blockDim.x + threadIdx.x; i < n8;
         i += (long)gridDim.x * blockDim.x) {
        long row = (i * 8) / E_;
        if (row < V_) {
            float4 v0 = neg4[i * 2];
            float4 v1 = neg4[i * 2 + 1];
            __half2 h0 = __float22half2_rn(make_float2(v0.x, v0.y));
            __half2 h1 = __float22half2_rn(make_float2(v0.z, v0.w));
            __half2 h2 = __float22half2_rn(make_float2(v1.x, v1.y));
            __half2 h3 = __float22half2_rn(make_float2(v1.z, v1.w));
            uint4 o = make_uint4(*reinterpret_cast<uint32_t*>(&h0),
                                 *reinterpret_cast<uint32_t*>(&h1),
                                 *reinterpret_cast<uint32_t*>(&h2),
                                 *reinterpret_cast<uint32_t*>(&h3));
            *reinterpret_cast<uint4*>(g_negh + i * 8) = o;
        } else {
            *reinterpret_cast<uint4*>(g_negh + i * 8) = make_uint4(0, 0, 0, 0);
        }
    }
}

// ---------------- K2: y[b] = EMBEDM[idx[b]] @ metric -> half ----------------
__global__ void embed_metric_kernel(const float* __restrict__ EMB,
                                    const float* __restrict__ metric) {
    __shared__ float xe[E_];
    const int b = blockIdx.x, t = threadIdx.x;   // 128 threads
    const int idx = g_idx[b];
    xe[t] = EMB[(size_t)idx * E_ + t];
    __syncthreads();
    float acc = 0.f;
#pragma unroll 8
    for (int k = 0; k < E_; k++) acc += xe[k] * metric[k * E_ + t];
    g_yh[b * E_ + t] = __float2half_rn(acc);
}

// ---------------- K3: persistent fp16 mma.sync GEMM + partials --------------
// 512 threads, 16 warps in 4(m)x4(n); warp tile 32x32 -> 32 accums/thread.
// smem: A half[128][128] swizzled @0 (32KB) | B0 @32768 | B1 @65536
#define SM_A   0
#define SM_B0  32768
#define SM_B1  65536
#define SMEM_BYTES 98304

// swizzled byte offset for (row, 16B-chunk c8) in a [128][256B] tile
__device__ __forceinline__ uint32_t swz(int row, int c8) {
    return (uint32_t)(row * 256 + ((c8 ^ (row & 7)) << 4));
}

__global__ void __launch_bounds__(512, 1)
gemm_lse_tc(float* __restrict__ out) {
    extern __shared__ char smc[];
    const uint32_t sbase = smem_u32(smc);

    const int tid = threadIdx.x;
    const int wid = tid >> 5, lane = tid & 31;
    const int warp_m = wid & 3, warp_n = wid >> 2;   // 4 x 4 warp grid
    const int qid = lane >> 2, tig = lane & 3;
    const int m0 = blockIdx.y * 128;

    // issue cp.async for B tile nt into buffer buf (data pre-padded)
    auto issueB = [&](int nt, int buf) {
        const int n0 = nt * 128;
        const uint32_t d0 = sbase + (buf ? SM_B1 : SM_B0);
#pragma unroll
        for (int f = tid; f < 2048; f += 512) {
            int row = f >> 4, c8 = f & 15;
            uint32_t dst = d0 + swz(row, c8);
            const char* src = reinterpret_cast<const char*>(g_negh)
                            + (size_t)(n0 + row) * 256 + c8 * 16;
            asm volatile("cp.async.cg.shared.global [%0], [%1], 16;"
                         :: "r"(dst), "l"(src) : "memory");
        }
        asm volatile("cp.async.commit_group;" ::: "memory");
    };

    issueB(blockIdx.x, 0);

    // ---- load A tile once (g_yh m-block) into swizzled smem ----
#pragma unroll
    for (int f = tid; f < 2048; f += 512) {
        int row = f >> 4, c8 = f & 15;
        uint4 v = *reinterpret_cast<const uint4*>(g_yh + (m0 + row) * E_ + c8 * 8);
        *reinterpret_cast<uint4*>(smc + SM_A + swz(row, c8)) = v;
    }

    int buf = 0;
    for (int nt = blockIdx.x; nt < NT_; nt += GX_, buf ^= 1) {
        const int ntn = nt + GX_;
        if (ntn < NT_) issueB(ntn, buf ^ 1);
        else asm volatile("cp.async.commit_group;" ::: "memory");
        asm volatile("cp.async.wait_group 1;" ::: "memory");
        __syncthreads();

        const uint32_t aB = sbase + SM_A;
        const uint32_t bB = sbase + (buf ? SM_B1 : SM_B0);

        float c[2][4][4];
#pragma unroll
        for (int mi = 0; mi < 2; mi++)
#pragma unroll
            for (int ni = 0; ni < 4; ni++)
#pragma unroll
                for (int j = 0; j < 4; j++) c[mi][ni][j] = 0.f;

#pragma unroll
        for (int ks = 0; ks < 8; ks++) {
            const int c8a = ks * 2 + (lane >> 4);           // A: lanes 16-31 -> k0+8
            const int c8b = ks * 2 + ((lane >> 3) & 1);     // B: lanes 8-15  -> k0+8
            uint32_t a[2][4], b[4][2];
#pragma unroll
            for (int mi = 0; mi < 2; mi++) {
                int row = warp_m * 32 + mi * 16 + (lane & 15);
                uint32_t addr = aB + swz(row, c8a);
                asm volatile("ldmatrix.sync.aligned.m8n8.x4.shared.b16 "
                             "{%0,%1,%2,%3}, [%4];"
                             : "=r"(a[mi][0]), "=r"(a[mi][1]),
                               "=r"(a[mi][2]), "=r"(a[mi][3]) : "r"(addr));
            }
#pragma unroll
            for (int ni = 0; ni < 4; ni++) {
                int nrow = warp_n * 32 + ni * 8 + (lane & 7);
                uint32_t addr = bB + swz(nrow, c8b);
                asm volatile("ldmatrix.sync.aligned.m8n8.x2.shared.b16 "
                             "{%0,%1}, [%2];"
                             : "=r"(b[ni][0]), "=r"(b[ni][1]) : "r"(addr));
            }
#pragma unroll
            for (int mi = 0; mi < 2; mi++)
#pragma unroll
                for (int ni = 0; ni < 4; ni++)
                    asm volatile(
                        "mma.sync.aligned.m16n8k16.row.col.f32.f16.f16.f32 "
                        "{%0,%1,%2,%3},{%4,%5,%6,%7},{%8,%9},{%0,%1,%2,%3};"
                        : "+f"(c[mi][ni][0]), "+f"(c[mi][ni][1]),
                          "+f"(c[mi][ni][2]), "+f"(c[mi][ni][3])
                        : "r"(a[mi][0]), "r"(a[mi][1]), "r"(a[mi][2]), "r"(a[mi][3]),
                          "r"(b[ni][0]), "r"(b[ni][1]));
        }
        __syncthreads();   // all B reads done before anyone prefetches into it

        // ---- epilogue: warp-local. streaming STG + per-warp row partials ----
        const int n0 = nt * 128;
        const int nvalid = min(128, V_ - n0);

#pragma unroll
        for (int mi = 0; mi < 2; mi++) {
            const int r0 = m0 + warp_m * 32 + mi * 16 + qid;
            float mxa = -INFINITY, mxb = -INFINITY;
#pragma unroll
            for (int ni = 0; ni < 4; ni++) {
                const int c0 = warp_n * 32 + ni * 8 + tig * 2;
                if (c0 < nvalid) {
                    __stcs(&out[(size_t)r0 * V_ + n0 + c0],       c[mi][ni][0]);
                    __stcs(&out[(size_t)(r0 + 8) * V_ + n0 + c0], c[mi][ni][2]);
                    mxa = fmaxf(mxa, c[mi][ni][0]);
                    mxb = fmaxf(mxb, c[mi][ni][2]);
                }
                if (c0 + 1 < nvalid) {
                    __stcs(&out[(size_t)r0 * V_ + n0 + c0 + 1],       c[mi][ni][1]);
                    __stcs(&out[(size_t)(r0 + 8) * V_ + n0 + c0 + 1], c[mi][ni][3]);
                    mxa = fmaxf(mxa, c[mi][ni][1]);
                    mxb = fmaxf(mxb, c[mi][ni][3]);
                }
            }
            mxa = fmaxf(mxa, __shfl_xor_sync(0xffffffffu, mxa, 1));
            mxa = fmaxf(mxa, __shfl_xor_sync(0xffffffffu, mxa, 2));
            mxb = fmaxf(mxb, __shfl_xor_sync(0xffffffffu, mxb, 1));
            mxb = fmaxf(mxb, __shfl_xor_sync(0xffffffffu, mxb, 2));
            float sa = 0.f, sb = 0.f;
#pragma unroll
            for (int ni = 0; ni < 4; ni++) {
                const int c0 = warp_n * 32 + ni * 8 + tig * 2;
                if (c0 < nvalid)     { sa += __expf(c[mi][ni][0] - mxa);
                                       sb += __expf(c[mi][ni][2] - mxb); }
                if (c0 + 1 < nvalid) { sa += __expf(c[mi][ni][1] - mxa);
                                       sb += __expf(c[mi][ni][3] - mxb); }
            }
            sa += __shfl_xor_sync(0xffffffffu, sa, 1);
            sa += __shfl_xor_sync(0xffffffffu, sa, 2);
            sb += __shfl_xor_sync(0xffffffffu, sb, 1);
            sb += __shfl_xor_sync(0xffffffffu, sb, 2);
            if (tig == 0) {
                g_part2[((size_t)r0 * NT_ + nt) * 4 + warp_n]       = make_float2(mxa, sa);
                g_part2[((size_t)(r0 + 8) * NT_ + nt) * 4 + warp_n] = make_float2(mxb, sb);
            }
        }
    }
}

// ---------------- K4: combine partials -> lse[b] ----------------------------
__global__ void lse_kernel() {
    const int b = blockIdx.x, t = threadIdx.x;   // 128 threads
    __shared__ float sm_[128], sl[128];
    const int NP = NT_ * 4;
    float m = -INFINITY, l = 0.f;
    for (int i = t; i < NP; i += 128) {
        float2 p = g_part2[(size_t)b * NP + i];
        float nm = fmaxf(m, p.x);
        l = l * expf(m - nm) + p.y * expf(p.x - nm);
        m = nm;
    }
    sm_[t] = m; sl[t] = l;
    __syncthreads();
    for (int s = 64; s > 0; s >>= 1) {
        if (t < s) {
            float m2 = sm_[t + s], l2 = sl[t + s];
            float nm = fmaxf(sm_[t], m2);
            sl[t] = sl[t] * expf(sm_[t] - nm) + l2 * expf(m2 - nm);
            sm_[t] = nm;
        }
        __syncthreads();
    }
    if (t == 0) g_lse[b] = sm_[0] + logf(sl[0]);
}

// ---------------- K5: out -= lse[b], vectorized ------------------------------
__global__ void sub_kernel(float4* __restrict__ out4) {
    const long n4 = (long)B_ * V_ / 4;
    for (long i = blockIdx.x * (long)blockDim.x + threadIdx.x; i < n4;
         i += (long)gridDim.x * blockDim.x) {
        long p = i * 4;
        int  b = (int)(p / V_);
        long rem = p - (long)b * V_;
        float4 v = out4[i];
        if (rem + 3 < V_) {
            float ls = g_lse[b];
            v.x -= ls; v.y -= ls; v.z -= ls; v.w -= ls;
        } else {
            v.x -= g_lse[b];
            v.y -= g_lse[(p + 1) / V_];
            v.z -= g_lse[(p + 2) / V_];
            v.w -= g_lse[(p + 3) / V_];
        }
        out4[i] = v;
    }
}

extern "C" void kernel_launch(void* const* d_in, const int* in_sizes, int n_in,
                              void* d_out, int out_size) {
    const float* xs     = (const float*)d_in[0];
    const float* metric = (const float*)d_in[1];
    const float* EMB    = (const float*)d_in[2];
    const float* NEG    = (const float*)d_in[3];
    float* out = (float*)d_out;

    conv_neg_kernel<<<1024, 256>>>((const float4*)NEG);
    find_idx_kernel<<<2048, 256>>>((const float4*)xs);
    embed_metric_kernel<<<B_, 128>>>(EMB, metric);

    cudaFuncSetAttribute(gemm_lse_tc,
                         cudaFuncAttributeMaxDynamicSharedMemorySize, SMEM_BYTES);
    gemm_lse_tc<<<dim3(GX_, 8), 512, SMEM_BYTES>>>(out);

    lse_kernel<<<B_, 128>>>();
    sub_kernel<<<2048, 256>>>((float4*)out);
}

// round 7
// speedup vs baseline: 1.0546x; 1.0546x over previous
#include <cuda_runtime.h>
#include <cuda_fp16.h>
#include <cstdint>
#include <math.h>

#define B_  1024
#define V_  50257
#define E_  128
#define NT_ 393          // ceil(V_/128)
#define VP_ (NT_ * 128)  // 50304 padded rows
#define GX_ 19           // n-split: 152 CTAs = 1 per SM

// ---- scratch (no allocations allowed) ----
__device__ int     g_idx[B_];
__device__ __half  g_yh[B_ * E_];
__device__ __half  g_negh[(size_t)VP_ * E_];      // padded half copy of NEGEMBEDM
__device__ float2  g_part2[(size_t)B_ * NT_ * 2]; // per-(row, tile, warp_n) partials
__device__ float   g_lse[B_];

__device__ __forceinline__ uint32_t smem_u32(const void* p) {
    uint32_t a;
    asm("{ .reg .u64 t; cvta.to.shared.u64 t, %1; cvt.u32.u64 %0, t; }"
        : "=r"(a) : "l"(p));
    return a;
}

// ---------------- K1: recover one-hot indices (bandwidth-bound scan) --------
__global__ void find_idx_kernel(const float4* __restrict__ xs4) {
    const long n4 = (long)B_ * V_ / 4;
    for (long i = blockIdx.x * (long)blockDim.x + threadIdx.x; i < n4;
         i += (long)gridDim.x * blockDim.x) {
        float4 v = xs4[i];
        if (v.x != 0.f || v.y != 0.f || v.z != 0.f || v.w != 0.f) {
            float vals[4] = {v.x, v.y, v.z, v.w};
            long base = i * 4;
#pragma unroll
            for (int j = 0; j < 4; j++) {
                if (vals[j] != 0.f) {
                    long p = base + j;
                    int  b = (int)(p / V_);
                    g_idx[b] = (int)(p - (long)b * V_);
                }
            }
        }
    }
}

// ---------------- K1b: convert NEGEMBEDM fp32 -> padded half ----------------
__global__ void conv_neg_kernel(const float4* __restrict__ neg4) {
    const long n8 = (long)VP_ * E_ / 8;   // 8 halves per iter
    for (long i = blockIdx.x * (long)blockDim.x + threadIdx.x; i < n8;
         i += (long)gridDim.x * blockDim.x) {
        long row = (i * 8) / E_;
        if (row < V_) {
            float4 v0 = neg4[i * 2];
            float4 v1 = neg4[i * 2 + 1];
            __half2 h0 = __float22half2_rn(make_float2(v0.x, v0.y));
            __half2 h1 = __float22half2_rn(make_float2(v0.z, v0.w));
            __half2 h2 = __float22half2_rn(make_float2(v1.x, v1.y));
            __half2 h3 = __float22half2_rn(make_float2(v1.z, v1.w));
            uint4 o = make_uint4(*reinterpret_cast<uint32_t*>(&h0),
                                 *reinterpret_cast<uint32_t*>(&h1),
                                 *reinterpret_cast<uint32_t*>(&h2),
                                 *reinterpret_cast<uint32_t*>(&h3));
            *reinterpret_cast<uint4*>(g_negh + i * 8) = o;
        } else {
            *reinterpret_cast<uint4*>(g_negh + i * 8) = make_uint4(0, 0, 0, 0);
        }
    }
}

// ---------------- K2: y[b] = EMBEDM[idx[b]] @ metric -> half ----------------
__global__ void embed_metric_kernel(const float* __restrict__ EMB,
                                    const float* __restrict__ metric) {
    __shared__ float xe[E_];
    const int b = blockIdx.x, t = threadIdx.x;   // 128 threads
    const int idx = g_idx[b];
    xe[t] = EMB[(size_t)idx * E_ + t];
    __syncthreads();
    float acc = 0.f;
#pragma unroll 8
    for (int k = 0; k < E_; k++) acc += xe[k] * metric[k * E_ + t];
    g_yh[b * E_ + t] = __float2half_rn(acc);
}

// ---------------- K3: persistent fp16 GEMM, A fragments register-resident ---
// 256 threads, 8 warps in 4(m) x 2(n); warp tile 32x64.
// A frags for the whole m-block/K loaded ONCE (64 regs); loop does B-ldmatrix
// + HMMA only.  smem: A half[128][128] swz @0 | B0 @32768 | B1 @65536
#define SM_A   0
#define SM_B0  32768
#define SM_B1  65536
#define SMEM_BYTES 98304

// swizzled byte offset for (row, 16B-chunk c8) in a [128][256B] tile
__device__ __forceinline__ uint32_t swz(int row, int c8) {
    return (uint32_t)(row * 256 + ((c8 ^ (row & 7)) << 4));
}

__global__ void __launch_bounds__(256, 1)
gemm_lse_tc(float* __restrict__ out) {
    extern __shared__ char smc[];
    const uint32_t sbase = smem_u32(smc);

    const int tid = threadIdx.x;
    const int wid = tid >> 5, lane = tid & 31;
    const int warp_m = wid & 3, warp_n = wid >> 2;   // 4(m) x 2(n)
    const int qid = lane >> 2, tig = lane & 3;
    const int m0 = blockIdx.y * 128;

    // issue cp.async for B tile nt into buffer buf (data pre-padded)
    auto issueB = [&](int nt, int buf) {
        const int n0 = nt * 128;
        const uint32_t d0 = sbase + (buf ? SM_B1 : SM_B0);
#pragma unroll
        for (int f = tid; f < 2048; f += 256) {
            int row = f >> 4, c8 = f & 15;
            uint32_t dst = d0 + swz(row, c8);
            const char* src = reinterpret_cast<const char*>(g_negh)
                            + (size_t)(n0 + row) * 256 + c8 * 16;
            asm volatile("cp.async.cg.shared.global [%0], [%1], 16;"
                         :: "r"(dst), "l"(src) : "memory");
        }
        asm volatile("cp.async.commit_group;" ::: "memory");
    };

    issueB(blockIdx.x, 0);

    // ---- stage A tile (g_yh m-block) into swizzled smem ----
#pragma unroll
    for (int f = tid; f < 2048; f += 256) {
        int row = f >> 4, c8 = f & 15;
        uint4 v = *reinterpret_cast<const uint4*>(g_yh + (m0 + row) * E_ + c8 * 8);
        *reinterpret_cast<uint4*>(smc + SM_A + swz(row, c8)) = v;
    }
    __syncthreads();

    // ---- load ALL A fragments into registers (persist across n-tiles) ----
    uint32_t afr[8][2][4];   // [ks][mi][frag]
#pragma unroll
    for (int ks = 0; ks < 8; ks++) {
        const int c8a = ks * 2 + (lane >> 4);
#pragma unroll
        for (int mi = 0; mi < 2; mi++) {
            int row = warp_m * 32 + mi * 16 + (lane & 15);
            uint32_t addr = sbase + SM_A + swz(row, c8a);
            asm volatile("ldmatrix.sync.aligned.m8n8.x4.shared.b16 "
                         "{%0,%1,%2,%3}, [%4];"
                         : "=r"(afr[ks][mi][0]), "=r"(afr[ks][mi][1]),
                           "=r"(afr[ks][mi][2]), "=r"(afr[ks][mi][3]) : "r"(addr));
        }
    }

    int buf = 0;
    for (int nt = blockIdx.x; nt < NT_; nt += GX_, buf ^= 1) {
        const int ntn = nt + GX_;
        if (ntn < NT_) issueB(ntn, buf ^ 1);
        else asm volatile("cp.async.commit_group;" ::: "memory");
        asm volatile("cp.async.wait_group 1;" ::: "memory");
        __syncthreads();

        const uint32_t bB = sbase + (buf ? SM_B1 : SM_B0);

        float c[2][8][4];
#pragma unroll
        for (int mi = 0; mi < 2; mi++)
#pragma unroll
            for (int ni = 0; ni < 8; ni++)
#pragma unroll
                for (int j = 0; j < 4; j++) c[mi][ni][j] = 0.f;

#pragma unroll
        for (int ks = 0; ks < 8; ks++) {
            const int c8b = ks * 2 + ((lane >> 3) & 1);     // lanes 8-15 -> k0+8
            uint32_t b[8][2];
#pragma unroll
            for (int ni = 0; ni < 8; ni++) {
                int nrow = warp_n * 64 + ni * 8 + (lane & 7);
                uint32_t addr = bB + swz(nrow, c8b);
                asm volatile("ldmatrix.sync.aligned.m8n8.x2.shared.b16 "
                             "{%0,%1}, [%2];"
                             : "=r"(b[ni][0]), "=r"(b[ni][1]) : "r"(addr));
            }
#pragma unroll
            for (int mi = 0; mi < 2; mi++)
#pragma unroll
                for (int ni = 0; ni < 8; ni++)
                    asm volatile(
                        "mma.sync.aligned.m16n8k16.row.col.f32.f16.f16.f32 "
                        "{%0,%1,%2,%3},{%4,%5,%6,%7},{%8,%9},{%0,%1,%2,%3};"
                        : "+f"(c[mi][ni][0]), "+f"(c[mi][ni][1]),
                          "+f"(c[mi][ni][2]), "+f"(c[mi][ni][3])
                        : "r"(afr[ks][mi][0]), "r"(afr[ks][mi][1]),
                          "r"(afr[ks][mi][2]), "r"(afr[ks][mi][3]),
                          "r"(b[ni][0]), "r"(b[ni][1]));
        }
        __syncthreads();   // all B reads done before anyone prefetches into it

        // ---- epilogue: warp-local stores + per-warp row partials ----
        const int n0 = nt * 128;
        const int nvalid = min(128, V_ - n0);

#pragma unroll
        for (int mi = 0; mi < 2; mi++) {
            const int r0 = m0 + warp_m * 32 + mi * 16 + qid;
            float mxa = -INFINITY, mxb = -INFINITY;
#pragma unroll
            for (int ni = 0; ni < 8; ni++) {
                const int cc = warp_n * 64 + ni * 8 + tig * 2;
                if (cc < nvalid) {
                    out[(size_t)r0 * V_ + n0 + cc]       = c[mi][ni][0];
                    out[(size_t)(r0 + 8) * V_ + n0 + cc] = c[mi][ni][2];
                    mxa = fmaxf(mxa, c[mi][ni][0]);
                    mxb = fmaxf(mxb, c[mi][ni][2]);
                }
                if (cc + 1 < nvalid) {
                    out[(size_t)r0 * V_ + n0 + cc + 1]       = c[mi][ni][1];
                    out[(size_t)(r0 + 8) * V_ + n0 + cc + 1] = c[mi][ni][3];
                    mxa = fmaxf(mxa, c[mi][ni][1]);
                    mxb = fmaxf(mxb, c[mi][ni][3]);
                }
            }
            mxa = fmaxf(mxa, __shfl_xor_sync(0xffffffffu, mxa, 1));
            mxa = fmaxf(mxa, __shfl_xor_sync(0xffffffffu, mxa, 2));
            mxb = fmaxf(mxb, __shfl_xor_sync(0xffffffffu, mxb, 1));
            mxb = fmaxf(mxb, __shfl_xor_sync(0xffffffffu, mxb, 2));
            float sa = 0.f, sb = 0.f;
#pragma unroll
            for (int ni = 0; ni < 8; ni++) {
                const int cc = warp_n * 64 + ni * 8 + tig * 2;
                if (cc < nvalid)     { sa += __expf(c[mi][ni][0] - mxa);
                                       sb += __expf(c[mi][ni][2] - mxb); }
                if (cc + 1 < nvalid) { sa += __expf(c[mi][ni][1] - mxa);
                                       sb += __expf(c[mi][ni][3] - mxb); }
            }
            sa += __shfl_xor_sync(0xffffffffu, sa, 1);
            sa += __shfl_xor_sync(0xffffffffu, sa, 2);
            sb += __shfl_xor_sync(0xffffffffu, sb, 1);
            sb += __shfl_xor_sync(0xffffffffu, sb, 2);
            if (tig == 0) {
                g_part2[((size_t)r0 * NT_ + nt) * 2 + warp_n]       = make_float2(mxa, sa);
                g_part2[((size_t)(r0 + 8) * NT_ + nt) * 2 + warp_n] = make_float2(mxb, sb);
            }
        }
    }
}

// ---------------- K4: combine partials -> lse[b] ----------------------------
__global__ void lse_kernel() {
    const int b = blockIdx.x, t = threadIdx.x;   // 128 threads
    __shared__ float sm_[128], sl[128];
    const int NP = NT_ * 2;
    float m = -INFINITY, l = 0.f;
    for (int i = t; i < NP; i += 128) {
        float2 p = g_part2[(size_t)b * NP + i];
        float nm = fmaxf(m, p.x);
        l = l * expf(m - nm) + p.y * expf(p.x - nm);
        m = nm;
    }
    sm_[t] = m; sl[t] = l;
    __syncthreads();
    for (int s = 64; s > 0; s >>= 1) {
        if (t < s) {
            float m2 = sm_[t + s], l2 = sl[t + s];
            float nm = fmaxf(sm_[t], m2);
            sl[t] = sl[t] * expf(sm_[t] - nm) + l2 * expf(m2 - nm);
            sm_[t] = nm;
        }
        __syncthreads();
    }
    if (t == 0) g_lse[b] = sm_[0] + logf(sl[0]);
}

// ---------------- K5: out -= lse[b], vectorized ------------------------------
__global__ void sub_kernel(float4* __restrict__ out4) {
    const long n4 = (long)B_ * V_ / 4;
    for (long i = blockIdx.x * (long)blockDim.x + threadIdx.x; i < n4;
         i += (long)gridDim.x * blockDim.x) {
        long p = i * 4;
        int  b = (int)(p / V_);
        long rem = p - (long)b * V_;
        float4 v = out4[i];
        if (rem + 3 < V_) {
            float ls = g_lse[b];
            v.x -= ls; v.y -= ls; v.z -= ls; v.w -= ls;
        } else {
            v.x -= g_lse[b];
            v.y -= g_lse[(p + 1) / V_];
            v.z -= g_lse[(p + 2) / V_];
            v.w -= g_lse[(p + 3) / V_];
        }
        out4[i] = v;
    }
}

extern "C" void kernel_launch(void* const* d_in, const int* in_sizes, int n_in,
                              void* d_out, int out_size) {
    const float* xs     = (const float*)d_in[0];
    const float* metric = (const float*)d_in[1];
    const float* EMB    = (const float*)d_in[2];
    const float* NEG    = (const float*)d_in[3];
    float* out = (float*)d_out;

    conv_neg_kernel<<<1024, 256>>>((const float4*)NEG);
    find_idx_kernel<<<2048, 256>>>((const float4*)xs);
    embed_metric_kernel<<<B_, 128>>>(EMB, metric);

    cudaFuncSetAttribute(gemm_lse_tc,
                         cudaFuncAttributeMaxDynamicSharedMemorySize, SMEM_BYTES);
    gemm_lse_tc<<<dim3(GX_, 8), 256, SMEM_BYTES>>>(out);

    lse_kernel<<<B_, 128>>>();
    sub_kernel<<<2048, 256>>>((float4*)out);
}

// round 8
// speedup vs baseline: 1.1654x; 1.1051x over previous
#include <cuda_runtime.h>
#include <cuda_fp16.h>
#include <cstdint>
#include <math.h>

#define B_  1024
#define V_  50257
#define E_  128
#define NT_ 393          // ceil(V_/128)
#define VP_ (NT_ * 128)  // 50304 padded rows
#define GX_ 19           // n-split: 152 CTAs = 1 per SM

// ---- scratch (no allocations allowed) ----
__device__ int     g_idx[B_];
__device__ __half  g_yh[B_ * E_];
__device__ __half  g_negh[(size_t)VP_ * E_];      // padded half copy of NEGEMBEDM
__device__ float2  g_part2[(size_t)B_ * NT_ * 4]; // per-(row, tile, warp_n) partials
__device__ float   g_lse[B_];

__device__ __forceinline__ uint32_t smem_u32(const void* p) {
    uint32_t a;
    asm("{ .reg .u64 t; cvta.to.shared.u64 t, %1; cvt.u32.u64 %0, t; }"
        : "=r"(a) : "l"(p));
    return a;
}

// ---------------- K1: fused conv(NEG->half, padded) + one-hot index scan ----
__global__ void prep_kernel(const float4* __restrict__ neg4,
                            const float4* __restrict__ xs4) {
    if (blockIdx.x < 1024) {
        // convert NEGEMBEDM fp32 -> padded half (8 halves / iter)
        const long n8 = (long)VP_ * E_ / 8;
        for (long i = blockIdx.x * (long)blockDim.x + threadIdx.x; i < n8;
             i += 1024L * blockDim.x) {
            long row = (i * 8) / E_;
            if (row < V_) {
                float4 v0 = neg4[i * 2];
                float4 v1 = neg4[i * 2 + 1];
                __half2 h0 = __float22half2_rn(make_float2(v0.x, v0.y));
                __half2 h1 = __float22half2_rn(make_float2(v0.z, v0.w));
                __half2 h2 = __float22half2_rn(make_float2(v1.x, v1.y));
                __half2 h3 = __float22half2_rn(make_float2(v1.z, v1.w));
                uint4 o = make_uint4(*reinterpret_cast<uint32_t*>(&h0),
                                     *reinterpret_cast<uint32_t*>(&h1),
                                     *reinterpret_cast<uint32_t*>(&h2),
                                     *reinterpret_cast<uint32_t*>(&h3));
                *reinterpret_cast<uint4*>(g_negh + i * 8) = o;
            } else {
                *reinterpret_cast<uint4*>(g_negh + i * 8) = make_uint4(0, 0, 0, 0);
            }
        }
    } else {
        // scan one-hot xs for indices
        const long n4 = (long)B_ * V_ / 4;
        for (long i = (blockIdx.x - 1024) * (long)blockDim.x + threadIdx.x; i < n4;
             i += 2048L * blockDim.x) {
            float4 v = xs4[i];
            if (v.x != 0.f || v.y != 0.f || v.z != 0.f || v.w != 0.f) {
                float vals[4] = {v.x, v.y, v.z, v.w};
                long base = i * 4;
#pragma unroll
                for (int j = 0; j < 4; j++) {
                    if (vals[j] != 0.f) {
                        long p = base + j;
                        int  b = (int)(p / V_);
                        g_idx[b] = (int)(p - (long)b * V_);
                    }
                }
            }
        }
    }
}

// ---------------- K2: y[b] = EMBEDM[idx[b]] @ metric -> half ----------------
__global__ void embed_metric_kernel(const float* __restrict__ EMB,
                                    const float* __restrict__ metric) {
    __shared__ float xe[E_];
    const int b = blockIdx.x, t = threadIdx.x;   // 128 threads
    const int idx = g_idx[b];
    xe[t] = EMB[(size_t)idx * E_ + t];
    __syncthreads();
    float acc = 0.f;
#pragma unroll 8
    for (int k = 0; k < E_; k++) acc += xe[k] * metric[k * E_ + t];
    g_yh[b * E_ + t] = __float2half_rn(acc);
}

// ---------------- K3: persistent fp16 GEMM, 3-stage pipeline ----------------
// 256 threads, 8 warps in 2(m) x 4(n); warp tile 64x32 (R4 layout).
// smem: A @0 (32KB) | B0 @32768 | B1 @65536 | B2 @98304
#define SM_A   0
#define SM_B0  32768
#define SMEM_BYTES 131072

// swizzled byte offset for (row, 16B-chunk c8) in a [128][256B] tile
__device__ __forceinline__ uint32_t swz(int row, int c8) {
    return (uint32_t)(row * 256 + ((c8 ^ (row & 7)) << 4));
}

// epilogue for one tile; FULL = all 128 columns valid
template<bool FULL>
__device__ __forceinline__ void epilogue(const float c[4][4][4],
                                         float* __restrict__ out,
                                         int m0, int n0, int nvalid,
                                         int warp_m, int warp_n,
                                         int qid, int tig, int nt) {
#pragma unroll
    for (int mi = 0; mi < 4; mi++) {
        const int r0 = m0 + warp_m * 64 + mi * 16 + qid;
        float* o0 = out + (size_t)r0 * V_ + n0 + warp_n * 32 + tig * 2;
        float* o1 = o0 + (size_t)8 * V_;
        float mxa = -INFINITY, mxb = -INFINITY;
#pragma unroll
        for (int ni = 0; ni < 4; ni++) {
            const int cc = ni * 8;
            if (FULL || warp_n * 32 + cc + tig * 2 < nvalid) {
                o0[cc]     = c[mi][ni][0];
                o1[cc]     = c[mi][ni][2];
                mxa = fmaxf(mxa, c[mi][ni][0]);
                mxb = fmaxf(mxb, c[mi][ni][2]);
            }
            if (FULL || warp_n * 32 + cc + tig * 2 + 1 < nvalid) {
                o0[cc + 1] = c[mi][ni][1];
                o1[cc + 1] = c[mi][ni][3];
                mxa = fmaxf(mxa, c[mi][ni][1]);
                mxb = fmaxf(mxb, c[mi][ni][3]);
            }
        }
        mxa = fmaxf(mxa, __shfl_xor_sync(0xffffffffu, mxa, 1));
        mxa = fmaxf(mxa, __shfl_xor_sync(0xffffffffu, mxa, 2));
        mxb = fmaxf(mxb, __shfl_xor_sync(0xffffffffu, mxb, 1));
        mxb = fmaxf(mxb, __shfl_xor_sync(0xffffffffu, mxb, 2));
        float sa = 0.f, sb = 0.f;
#pragma unroll
        for (int ni = 0; ni < 4; ni++) {
            const int cc = warp_n * 32 + ni * 8 + tig * 2;
            if (FULL || cc < nvalid)     { sa += __expf(c[mi][ni][0] - mxa);
                                           sb += __expf(c[mi][ni][2] - mxb); }
            if (FULL || cc + 1 < nvalid) { sa += __expf(c[mi][ni][1] - mxa);
                                           sb += __expf(c[mi][ni][3] - mxb); }
        }
        sa += __shfl_xor_sync(0xffffffffu, sa, 1);
        sa += __shfl_xor_sync(0xffffffffu, sa, 2);
        sb += __shfl_xor_sync(0xffffffffu, sb, 1);
        sb += __shfl_xor_sync(0xffffffffu, sb, 2);
        if (tig == 0) {
            g_part2[((size_t)r0 * NT_ + nt) * 4 + warp_n]       = make_float2(mxa, sa);
            g_part2[((size_t)(r0 + 8) * NT_ + nt) * 4 + warp_n] = make_float2(mxb, sb);
        }
    }
}

__global__ void __launch_bounds__(256, 1)
gemm_lse_tc(float* __restrict__ out) {
    extern __shared__ char smc[];
    const uint32_t sbase = smem_u32(smc);

    const int tid = threadIdx.x;
    const int wid = tid >> 5, lane = tid & 31;
    const int warp_m = wid & 1, warp_n = wid >> 1;   // 2(m) x 4(n)
    const int qid = lane >> 2, tig = lane & 3;
    const int m0 = blockIdx.y * 128;

    // issue cp.async for B tile nt into buffer buf (empty commit past end)
    auto issueB = [&](int nt, int buf) {
        if (nt < NT_) {
            const int n0 = nt * 128;
            const uint32_t d0 = sbase + SM_B0 + (buf << 15);
#pragma unroll
            for (int f = tid; f < 2048; f += 256) {
                int row = f >> 4, c8 = f & 15;
                uint32_t dst = d0 + swz(row, c8);
                const char* src = reinterpret_cast<const char*>(g_negh)
                                + (size_t)(n0 + row) * 256 + c8 * 16;
                asm volatile("cp.async.cg.shared.global [%0], [%1], 16;"
                             :: "r"(dst), "l"(src) : "memory");
            }
        }
        asm volatile("cp.async.commit_group;" ::: "memory");
    };

    issueB(blockIdx.x, 0);
    issueB(blockIdx.x + GX_, 1);

    // ---- stage A tile (g_yh m-block) into swizzled smem ----
#pragma unroll
    for (int f = tid; f < 2048; f += 256) {
        int row = f >> 4, c8 = f & 15;
        uint4 v = *reinterpret_cast<const uint4*>(g_yh + (m0 + row) * E_ + c8 * 8);
        *reinterpret_cast<uint4*>(smc + SM_A + swz(row, c8)) = v;
    }

    int idx = 0;
    for (int nt = blockIdx.x; nt < NT_; nt += GX_, idx++) {
        asm volatile("cp.async.wait_group 1;" ::: "memory");
        __syncthreads();

        const uint32_t aB = sbase + SM_A;
        const int bsel = idx - (idx / 3) * 3;
        const uint32_t bB = sbase + SM_B0 + (bsel << 15);

        float c[4][4][4];
#pragma unroll
        for (int mi = 0; mi < 4; mi++)
#pragma unroll
            for (int ni = 0; ni < 4; ni++)
#pragma unroll
                for (int j = 0; j < 4; j++) c[mi][ni][j] = 0.f;

#pragma unroll
        for (int ks = 0; ks < 8; ks++) {
            const int c8a = ks * 2 + (lane >> 4);           // A: lanes 16-31 -> k0+8
            uint32_t a[4][4], b[4][2];
#pragma unroll
            for (int mi = 0; mi < 4; mi++) {
                int row = warp_m * 64 + mi * 16 + (lane & 15);
                uint32_t addr = aB + swz(row, c8a);
                asm volatile("ldmatrix.sync.aligned.m8n8.x4.shared.b16 "
                             "{%0,%1,%2,%3}, [%4];"
                             : "=r"(a[mi][0]), "=r"(a[mi][1]),
                               "=r"(a[mi][2]), "=r"(a[mi][3]) : "r"(addr));
            }
            // B: 2 x4-ldmatrix, each covering an ni pair x both k-halves
#pragma unroll
            for (int j = 0; j < 2; j++) {
                const int g = lane >> 3;                    // lane group 0..3
                int ni_x = 2 * j + (g >> 1);
                int half = g & 1;
                int nrow = warp_n * 32 + ni_x * 8 + (lane & 7);
                uint32_t addr = bB + swz(nrow, ks * 2 + half);
                asm volatile("ldmatrix.sync.aligned.m8n8.x4.shared.b16 "
                             "{%0,%1,%2,%3}, [%4];"
                             : "=r"(b[2 * j][0]), "=r"(b[2 * j][1]),
                               "=r"(b[2 * j + 1][0]), "=r"(b[2 * j + 1][1])
                             : "r"(addr));
            }
#pragma unroll
            for (int mi = 0; mi < 4; mi++)
#pragma unroll
                for (int ni = 0; ni < 4; ni++)
                    asm volatile(
                        "mma.sync.aligned.m16n8k16.row.col.f32.f16.f16.f32 "
                        "{%0,%1,%2,%3},{%4,%5,%6,%7},{%8,%9},{%0,%1,%2,%3};"
                        : "+f"(c[mi][ni][0]), "+f"(c[mi][ni][1]),
                          "+f"(c[mi][ni][2]), "+f"(c[mi][ni][3])
                        : "r"(a[mi][0]), "r"(a[mi][1]), "r"(a[mi][2]), "r"(a[mi][3]),
                          "r"(b[ni][0]), "r"(b[ni][1]));
        }
        __syncthreads();   // all reads of buf idx%3 done (frees idx-1's buffer slot)

        issueB(nt + 2 * GX_, (bsel + 2 >= 3) ? bsel - 1 : bsel + 2);

        const int n0 = nt * 128;
        const int nvalid = min(128, V_ - n0);
        if (nvalid == 128)
            epilogue<true >(c, out, m0, n0, nvalid, warp_m, warp_n, qid, tig, nt);
        else
            epilogue<false>(c, out, m0, n0, nvalid, warp_m, warp_n, qid, tig, nt);
    }
}

// ---------------- K4: combine partials -> lse[b] ----------------------------
__global__ void lse_kernel() {
    const int b = blockIdx.x, t = threadIdx.x;   // 128 threads
    __shared__ float sm_[128], sl[128];
    const int NP = NT_ * 4;
    float m = -INFINITY, l = 0.f;
    for (int i = t; i < NP; i += 128) {
        float2 p = g_part2[(size_t)b * NP + i];
        float nm = fmaxf(m, p.x);
        l = l * expf(m - nm) + p.y * expf(p.x - nm);
        m = nm;
    }
    sm_[t] = m; sl[t] = l;
    __syncthreads();
    for (int s = 64; s > 0; s >>= 1) {
        if (t < s) {
            float m2 = sm_[t + s], l2 = sl[t + s];
            float nm = fmaxf(sm_[t], m2);
            sl[t] = sl[t] * expf(sm_[t] - nm) + l2 * expf(m2 - nm);
            sm_[t] = nm;
        }
        __syncthreads();
    }
    if (t == 0) g_lse[b] = sm_[0] + logf(sl[0]);
}

// ---------------- K5: out -= lse[b], vectorized ------------------------------
__global__ void sub_kernel(float4* __restrict__ out4) {
    const long n4 = (long)B_ * V_ / 4;
    for (long i = blockIdx.x * (long)blockDim.x + threadIdx.x; i < n4;
         i += (long)gridDim.x * blockDim.x) {
        long p = i * 4;
        int  b = (int)(p / V_);
        long rem = p - (long)b * V_;
        float4 v = out4[i];
        if (rem + 3 < V_) {
            float ls = g_lse[b];
            v.x -= ls; v.y -= ls; v.z -= ls; v.w -= ls;
        } else {
            v.x -= g_lse[b];
            v.y -= g_lse[(p + 1) / V_];
            v.z -= g_lse[(p + 2) / V_];
            v.w -= g_lse[(p + 3) / V_];
        }
        out4[i] = v;
    }
}

extern "C" void kernel_launch(void* const* d_in, const int* in_sizes, int n_in,
                              void* d_out, int out_size) {
    const float* xs     = (const float*)d_in[0];
    const float* metric = (const float*)d_in[1];
    const float* EMB    = (const float*)d_in[2];
    const float* NEG    = (const float*)d_in[3];
    float* out = (float*)d_out;

    prep_kernel<<<3072, 256>>>((const float4*)NEG, (const float4*)xs);
    embed_metric_kernel<<<B_, 128>>>(EMB, metric);

    cudaFuncSetAttribute(gemm_lse_tc,
                         cudaFuncAttributeMaxDynamicSharedMemorySize, SMEM_BYTES);
    gemm_lse_tc<<<dim3(GX_, 8), 256, SMEM_BYTES>>>(out);

    lse_kernel<<<B_, 128>>>();
    sub_kernel<<<2048, 256>>>((float4*)out);
}

// round 9
// speedup vs baseline: 1.4197x; 1.2182x over previous
#include <cuda_runtime.h>
#include <cuda_fp16.h>
#include <cstdint>
#include <math.h>

#define B_  1024
#define V_  50257
#define E_  128
#define NT_ 393          // ceil(V_/128)
#define VP_ (NT_ * 128)  // 50304 padded rows
#define GX_ 19           // n-split: 152 CTAs = 1 per SM

// ---- scratch (no allocations allowed) ----
__device__ int     g_idx[B_];
__device__ __half  g_yh[B_ * E_];
__device__ __half  g_negh[(size_t)VP_ * E_];      // padded half copy of NEGEMBEDM
__device__ float2  g_part2[(size_t)B_ * NT_ * 4]; // per-(row, tile, warp_n) partials
__device__ float   g_lse[B_];

__device__ __forceinline__ uint32_t smem_u32(const void* p) {
    uint32_t a;
    asm("{ .reg .u64 t; cvta.to.shared.u64 t, %1; cvt.u32.u64 %0, t; }"
        : "=r"(a) : "l"(p));
    return a;
}

// ---------------- K1: fused conv(NEG->half, padded) + one-hot index scan ----
__global__ void prep_kernel(const float4* __restrict__ neg4,
                            const float4* __restrict__ xs4) {
    if (blockIdx.x < 1024) {
        const long n8 = (long)VP_ * E_ / 8;
        for (long i = blockIdx.x * (long)blockDim.x + threadIdx.x; i < n8;
             i += 1024L * blockDim.x) {
            long row = (i * 8) / E_;
            if (row < V_) {
                float4 v0 = neg4[i * 2];
                float4 v1 = neg4[i * 2 + 1];
                __half2 h0 = __float22half2_rn(make_float2(v0.x, v0.y));
                __half2 h1 = __float22half2_rn(make_float2(v0.z, v0.w));
                __half2 h2 = __float22half2_rn(make_float2(v1.x, v1.y));
                __half2 h3 = __float22half2_rn(make_float2(v1.z, v1.w));
                uint4 o = make_uint4(*reinterpret_cast<uint32_t*>(&h0),
                                     *reinterpret_cast<uint32_t*>(&h1),
                                     *reinterpret_cast<uint32_t*>(&h2),
                                     *reinterpret_cast<uint32_t*>(&h3));
                *reinterpret_cast<uint4*>(g_negh + i * 8) = o;
            } else {
                *reinterpret_cast<uint4*>(g_negh + i * 8) = make_uint4(0, 0, 0, 0);
            }
        }
    } else {
        const long n4 = (long)B_ * V_ / 4;
        for (long i = (blockIdx.x - 1024) * (long)blockDim.x + threadIdx.x; i < n4;
             i += 2048L * blockDim.x) {
            float4 v = xs4[i];
            if (v.x != 0.f || v.y != 0.f || v.z != 0.f || v.w != 0.f) {
                float vals[4] = {v.x, v.y, v.z, v.w};
                long base = i * 4;
#pragma unroll
                for (int j = 0; j < 4; j++) {
                    if (vals[j] != 0.f) {
                        long p = base + j;
                        int  b = (int)(p / V_);
                        g_idx[b] = (int)(p - (long)b * V_);
                    }
                }
            }
        }
    }
}

// ---------------- K2: y[b] = EMBEDM[idx[b]] @ metric -> half ----------------
__global__ void embed_metric_kernel(const float* __restrict__ EMB,
                                    const float* __restrict__ metric) {
    __shared__ float xe[E_];
    const int b = blockIdx.x, t = threadIdx.x;   // 128 threads
    const int idx = g_idx[b];
    xe[t] = EMB[(size_t)idx * E_ + t];
    __syncthreads();
    float acc = 0.f;
#pragma unroll 8
    for (int k = 0; k < E_; k++) acc += xe[k] * metric[k * E_ + t];
    g_yh[b * E_ + t] = __float2half_rn(acc);
}

// ---------------- K3: persistent fp16 GEMM, staged coalesced epilogue -------
// 256 threads, 8 warps in 2(m) x 4(n); warp tile 64x32.
// smem: A @0 (32KB) | B0/B1/B2 @32768+ (96KB) | C float[128][132] @131072
#define SM_A   0
#define SM_B0  32768
#define SM_C   131072
#define CPAD   132
#define SMEM_BYTES (131072 + 128 * CPAD * 4)   // 198656

// swizzled byte offset for (row, 16B-chunk c8) in a [128][256B] tile
__device__ __forceinline__ uint32_t swz(int row, int c8) {
    return (uint32_t)(row * 256 + ((c8 ^ (row & 7)) << 4));
}

// per-warp softmax partials from register fragments; FULL = all 128 cols valid
template<bool FULL>
__device__ __forceinline__ void partials(const float c[4][4][4], int nvalid,
                                         int m0, int n0, int warp_m, int warp_n,
                                         int qid, int tig, int nt) {
#pragma unroll
    for (int mi = 0; mi < 4; mi++) {
        const int r0 = m0 + warp_m * 64 + mi * 16 + qid;
        float mxa = -INFINITY, mxb = -INFINITY;
        float sa = 0.f, sb = 0.f;
#pragma unroll
        for (int ni = 0; ni < 4; ni++) {
            const int cc = warp_n * 32 + ni * 8 + tig * 2;
            if (FULL || cc < nvalid) {
                mxa = fmaxf(mxa, c[mi][ni][0]);
                mxb = fmaxf(mxb, c[mi][ni][2]);
            }
            if (FULL || cc + 1 < nvalid) {
                mxa = fmaxf(mxa, c[mi][ni][1]);
                mxb = fmaxf(mxb, c[mi][ni][3]);
            }
        }
        mxa = fmaxf(mxa, __shfl_xor_sync(0xffffffffu, mxa, 1));
        mxa = fmaxf(mxa, __shfl_xor_sync(0xffffffffu, mxa, 2));
        mxb = fmaxf(mxb, __shfl_xor_sync(0xffffffffu, mxb, 1));
        mxb = fmaxf(mxb, __shfl_xor_sync(0xffffffffu, mxb, 2));
#pragma unroll
        for (int ni = 0; ni < 4; ni++) {
            const int cc = warp_n * 32 + ni * 8 + tig * 2;
            if (FULL || cc < nvalid)     { sa += __expf(c[mi][ni][0] - mxa);
                                           sb += __expf(c[mi][ni][2] - mxb); }
            if (FULL || cc + 1 < nvalid) { sa += __expf(c[mi][ni][1] - mxa);
                                           sb += __expf(c[mi][ni][3] - mxb); }
        }
        sa += __shfl_xor_sync(0xffffffffu, sa, 1);
        sa += __shfl_xor_sync(0xffffffffu, sa, 2);
        sb += __shfl_xor_sync(0xffffffffu, sb, 1);
        sb += __shfl_xor_sync(0xffffffffu, sb, 2);
        if (tig == 0) {
            g_part2[((size_t)r0 * NT_ + nt) * 4 + warp_n]       = make_float2(mxa, sa);
            g_part2[((size_t)(r0 + 8) * NT_ + nt) * 4 + warp_n] = make_float2(mxb, sb);
        }
    }
}

__global__ void __launch_bounds__(256, 1)
gemm_lse_tc(float* __restrict__ out) {
    extern __shared__ char smc[];
    const uint32_t sbase = smem_u32(smc);
    float* Cs = reinterpret_cast<float*>(smc + SM_C);

    const int tid = threadIdx.x;
    const int wid = tid >> 5, lane = tid & 31;
    const int warp_m = wid & 1, warp_n = wid >> 1;   // 2(m) x 4(n)
    const int qid = lane >> 2, tig = lane & 3;
    const int m0 = blockIdx.y * 128;

    auto issueB = [&](int nt, int buf) {
        if (nt < NT_) {
            const int n0 = nt * 128;
            const uint32_t d0 = sbase + SM_B0 + (buf << 15);
#pragma unroll
            for (int f = tid; f < 2048; f += 256) {
                int row = f >> 4, c8 = f & 15;
                uint32_t dst = d0 + swz(row, c8);
                const char* src = reinterpret_cast<const char*>(g_negh)
                                + (size_t)(n0 + row) * 256 + c8 * 16;
                asm volatile("cp.async.cg.shared.global [%0], [%1], 16;"
                             :: "r"(dst), "l"(src) : "memory");
            }
        }
        asm volatile("cp.async.commit_group;" ::: "memory");
    };

    issueB(blockIdx.x, 0);
    issueB(blockIdx.x + GX_, 1);

    // ---- stage A tile (g_yh m-block) into swizzled smem ----
#pragma unroll
    for (int f = tid; f < 2048; f += 256) {
        int row = f >> 4, c8 = f & 15;
        uint4 v = *reinterpret_cast<const uint4*>(g_yh + (m0 + row) * E_ + c8 * 8);
        *reinterpret_cast<uint4*>(smc + SM_A + swz(row, c8)) = v;
    }

    int idx = 0;
    for (int nt = blockIdx.x; nt < NT_; nt += GX_, idx++) {
        asm volatile("cp.async.wait_group 1;" ::: "memory");
        __syncthreads();

        const uint32_t aB = sbase + SM_A;
        const int bsel = idx - (idx / 3) * 3;
        const uint32_t bB = sbase + SM_B0 + (bsel << 15);

        float c[4][4][4];
#pragma unroll
        for (int mi = 0; mi < 4; mi++)
#pragma unroll
            for (int ni = 0; ni < 4; ni++)
#pragma unroll
                for (int j = 0; j < 4; j++) c[mi][ni][j] = 0.f;

#pragma unroll
        for (int ks = 0; ks < 8; ks++) {
            const int c8a = ks * 2 + (lane >> 4);
            uint32_t a[4][4], b[4][2];
#pragma unroll
            for (int mi = 0; mi < 4; mi++) {
                int row = warp_m * 64 + mi * 16 + (lane & 15);
                uint32_t addr = aB + swz(row, c8a);
                asm volatile("ldmatrix.sync.aligned.m8n8.x4.shared.b16 "
                             "{%0,%1,%2,%3}, [%4];"
                             : "=r"(a[mi][0]), "=r"(a[mi][1]),
                               "=r"(a[mi][2]), "=r"(a[mi][3]) : "r"(addr));
            }
#pragma unroll
            for (int j = 0; j < 2; j++) {
                const int g = lane >> 3;
                int ni_x = 2 * j + (g >> 1);
                int half = g & 1;
                int nrow = warp_n * 32 + ni_x * 8 + (lane & 7);
                uint32_t addr = bB + swz(nrow, ks * 2 + half);
                asm volatile("ldmatrix.sync.aligned.m8n8.x4.shared.b16 "
                             "{%0,%1,%2,%3}, [%4];"
                             : "=r"(b[2 * j][0]), "=r"(b[2 * j][1]),
                               "=r"(b[2 * j + 1][0]), "=r"(b[2 * j + 1][1])
                             : "r"(addr));
            }
#pragma unroll
            for (int mi = 0; mi < 4; mi++)
#pragma unroll
                for (int ni = 0; ni < 4; ni++)
                    asm volatile(
                        "mma.sync.aligned.m16n8k16.row.col.f32.f16.f16.f32 "
                        "{%0,%1,%2,%3},{%4,%5,%6,%7},{%8,%9},{%0,%1,%2,%3};"
                        : "+f"(c[mi][ni][0]), "+f"(c[mi][ni][1]),
                          "+f"(c[mi][ni][2]), "+f"(c[mi][ni][3])
                        : "r"(a[mi][0]), "r"(a[mi][1]), "r"(a[mi][2]), "r"(a[mi][3]),
                          "r"(b[ni][0]), "r"(b[ni][1]));
        }
        __syncthreads();   // all reads of this B buffer done

        issueB(nt + 2 * GX_, (bsel + 2 >= 3) ? bsel - 1 : bsel + 2);

        const int n0 = nt * 128;
        const int nvalid = min(128, V_ - n0);
        if (nvalid == 128) partials<true >(c, nvalid, m0, n0, warp_m, warp_n, qid, tig, nt);
        else               partials<false>(c, nvalid, m0, n0, warp_m, warp_n, qid, tig, nt);

        // ---- stage C into smem (float2, even addresses; <=2-way conflicts) ----
#pragma unroll
        for (int mi = 0; mi < 4; mi++) {
            const int r0 = warp_m * 64 + mi * 16 + qid;
            float* c0p = Cs + r0 * CPAD + warp_n * 32 + tig * 2;
#pragma unroll
            for (int ni = 0; ni < 4; ni++) {
                *reinterpret_cast<float2*>(c0p + ni * 8) =
                    make_float2(c[mi][ni][0], c[mi][ni][1]);
                *reinterpret_cast<float2*>(c0p + ni * 8 + 8 * CPAD) =
                    make_float2(c[mi][ni][2], c[mi][ni][3]);
            }
        }
        __syncthreads();

        // ---- coalesced copy: warp owns rows [wid*16, wid*16+16) ----
        if (nvalid == 128) {
#pragma unroll
            for (int j = 0; j < 16; j++) {
                const int row = (wid << 4) + j;
                const float* cs = Cs + row * CPAD;
                float* ob = out + (size_t)(m0 + row) * V_ + n0;
                if (!(row & 1)) {        // even global address base
#pragma unroll
                    for (int k = 0; k < 2; k++) {
                        int col = ((k << 5) + lane) << 1;
                        *reinterpret_cast<float2*>(ob + col) =
                            make_float2(cs[col], cs[col + 1]);
                    }
                } else {                 // odd base: scalar head/tail, f2 body
                    if (lane == 0)  ob[0]   = cs[0];
                    if (lane == 31) ob[127] = cs[127];
#pragma unroll
                    for (int k = 0; k < 2; k++) {
                        int i2 = (k << 5) + lane;
                        if (i2 < 63) {
                            int col = 1 + (i2 << 1);
                            *reinterpret_cast<float2*>(ob + col) =
                                make_float2(cs[col], cs[col + 1]);
                        }
                    }
                }
            }
        } else {
            for (int j = 0; j < 16; j++) {
                const int row = (wid << 4) + j;
                const float* cs = Cs + row * CPAD;
                float* ob = out + (size_t)(m0 + row) * V_ + n0;
                for (int col = lane; col < nvalid; col += 32)
                    ob[col] = cs[col];
            }
        }
        // loop-top __syncthreads protects Cs reuse next iteration
    }
}

// ---------------- K4: combine partials -> lse[b] ----------------------------
__global__ void lse_kernel() {
    const int b = blockIdx.x, t = threadIdx.x;   // 128 threads
    __shared__ float sm_[128], sl[128];
    const int NP = NT_ * 4;
    float m = -INFINITY, l = 0.f;
    for (int i = t; i < NP; i += 128) {
        float2 p = g_part2[(size_t)b * NP + i];
        float nm = fmaxf(m, p.x);
        l = l * expf(m - nm) + p.y * expf(p.x - nm);
        m = nm;
    }
    sm_[t] = m; sl[t] = l;
    __syncthreads();
    for (int s = 64; s > 0; s >>= 1) {
        if (t < s) {
            float m2 = sm_[t + s], l2 = sl[t + s];
            float nm = fmaxf(sm_[t], m2);
            sl[t] = sl[t] * expf(sm_[t] - nm) + l2 * expf(m2 - nm);
            sm_[t] = nm;
        }
        __syncthreads();
    }
    if (t == 0) g_lse[b] = sm_[0] + logf(sl[0]);
}

// ---------------- K5: out -= lse[b], vectorized ------------------------------
__global__ void sub_kernel(float4* __restrict__ out4) {
    const long n4 = (long)B_ * V_ / 4;
    for (long i = blockIdx.x * (long)blockDim.x + threadIdx.x; i < n4;
         i += (long)gridDim.x * blockDim.x) {
        long p = i * 4;
        int  b = (int)(p / V_);
        long rem = p - (long)b * V_;
        float4 v = out4[i];
        if (rem + 3 < V_) {
            float ls = g_lse[b];
            v.x -= ls; v.y -= ls; v.z -= ls; v.w -= ls;
        } else {
            v.x -= g_lse[b];
            v.y -= g_lse[(p + 1) / V_];
            v.z -= g_lse[(p + 2) / V_];
            v.w -= g_lse[(p + 3) / V_];
        }
        out4[i] = v;
    }
}

extern "C" void kernel_launch(void* const* d_in, const int* in_sizes, int n_in,
                              void* d_out, int out_size) {
    const float* xs     = (const float*)d_in[0];
    const float* metric = (const float*)d_in[1];
    const float* EMB    = (const float*)d_in[2];
    const float* NEG    = (const float*)d_in[3];
    float* out = (float*)d_out;

    prep_kernel<<<3072, 256>>>((const float4*)NEG, (const float4*)xs);
    embed_metric_kernel<<<B_, 128>>>(EMB, metric);

    cudaFuncSetAttribute(gemm_lse_tc,
                         cudaFuncAttributeMaxDynamicSharedMemorySize, SMEM_BYTES);
    gemm_lse_tc<<<dim3(GX_, 8), 256, SMEM_BYTES>>>(out);

    lse_kernel<<<B_, 128>>>();
    sub_kernel<<<2048, 256>>>((float4*)out);
}

// round 10
// speedup vs baseline: 1.6212x; 1.1419x over previous
#include <cuda_runtime.h>
#include <cuda_fp16.h>
#include <cstdint>
#include <math.h>

#define B_  1024
#define V_  50257
#define E_  128
#define NT_ 393          // ceil(V_/128)
#define VP_ (NT_ * 128)  // 50304 padded rows
#define GX_ 19           // n-split: 152 CTAs = 1 per SM

// ---- scratch (no allocations allowed) ----
__device__ int     g_idx[B_];
__device__ __half  g_yh[B_ * E_];
__device__ __half  g_negh[(size_t)VP_ * E_];      // padded half copy of NEGEMBEDM
__device__ float2  g_part2[(size_t)B_ * NT_ * 4]; // per-(row, tile, warp_n) partials
__device__ float   g_lse[B_];

__device__ __forceinline__ uint32_t smem_u32(const void* p) {
    uint32_t a;
    asm("{ .reg .u64 t; cvta.to.shared.u64 t, %1; cvt.u32.u64 %0, t; }"
        : "=r"(a) : "l"(p));
    return a;
}

// ---------------- K1: fused conv(NEG->half, padded) + one-hot index scan ----
__global__ void prep_kernel(const float4* __restrict__ neg4,
                            const float4* __restrict__ xs4) {
    if (blockIdx.x < 1024) {
        const long n8 = (long)VP_ * E_ / 8;
        for (long i = blockIdx.x * (long)blockDim.x + threadIdx.x; i < n8;
             i += 1024L * blockDim.x) {
            long row = (i * 8) / E_;
            if (row < V_) {
                float4 v0 = neg4[i * 2];
                float4 v1 = neg4[i * 2 + 1];
                __half2 h0 = __float22half2_rn(make_float2(v0.x, v0.y));
                __half2 h1 = __float22half2_rn(make_float2(v0.z, v0.w));
                __half2 h2 = __float22half2_rn(make_float2(v1.x, v1.y));
                __half2 h3 = __float22half2_rn(make_float2(v1.z, v1.w));
                uint4 o = make_uint4(*reinterpret_cast<uint32_t*>(&h0),
                                     *reinterpret_cast<uint32_t*>(&h1),
                                     *reinterpret_cast<uint32_t*>(&h2),
                                     *reinterpret_cast<uint32_t*>(&h3));
                *reinterpret_cast<uint4*>(g_negh + i * 8) = o;
            } else {
                *reinterpret_cast<uint4*>(g_negh + i * 8) = make_uint4(0, 0, 0, 0);
            }
        }
    } else {
        const long n4 = (long)B_ * V_ / 4;
        for (long i = (blockIdx.x - 1024) * (long)blockDim.x + threadIdx.x; i < n4;
             i += 2048L * blockDim.x) {
            float4 v = xs4[i];
            if (v.x != 0.f || v.y != 0.f || v.z != 0.f || v.w != 0.f) {
                float vals[4] = {v.x, v.y, v.z, v.w};
                long base = i * 4;
#pragma unroll
                for (int j = 0; j < 4; j++) {
                    if (vals[j] != 0.f) {
                        long p = base + j;
                        int  b = (int)(p / V_);
                        g_idx[b] = (int)(p - (long)b * V_);
                    }
                }
            }
        }
    }
}

// ---------------- K2: y[b] = EMBEDM[idx[b]] @ metric -> half ----------------
__global__ void embed_metric_kernel(const float* __restrict__ EMB,
                                    const float* __restrict__ metric) {
    __shared__ float xe[E_];
    const int b = blockIdx.x, t = threadIdx.x;   // 128 threads
    const int idx = g_idx[b];
    xe[t] = EMB[(size_t)idx * E_ + t];
    __syncthreads();
    float acc = 0.f;
#pragma unroll 8
    for (int k = 0; k < E_; k++) acc += xe[k] * metric[k * E_ + t];
    g_yh[b * E_ + t] = __float2half_rn(acc);
}

// ---------------- K3: persistent fp16 GEMM, two passes ----------------------
// Pass 1 (WRITE=false): mainloop + per-warp softmax partials, no stores.
// Pass 2 (WRITE=true):  mainloop + (score - lse) staged coalesced store.
// 256 threads, 8 warps in 2(m) x 4(n); warp tile 64x32.
// smem: A @0 (32KB) | B0/B1/B2 @32768+ (96KB) | C float[128][132] @131072
#define SM_A   0
#define SM_B0  32768
#define SM_C   131072
#define CPAD   132
#define SMEM_BYTES (131072 + 128 * CPAD * 4)   // 198656

__device__ __forceinline__ uint32_t swz(int row, int c8) {
    return (uint32_t)(row * 256 + ((c8 ^ (row & 7)) << 4));
}

template<bool FULL>
__device__ __forceinline__ void partials(const float c[4][4][4], int nvalid,
                                         int m0, int n0, int warp_m, int warp_n,
                                         int qid, int tig, int nt) {
#pragma unroll
    for (int mi = 0; mi < 4; mi++) {
        const int r0 = m0 + warp_m * 64 + mi * 16 + qid;
        float mxa = -INFINITY, mxb = -INFINITY;
        float sa = 0.f, sb = 0.f;
#pragma unroll
        for (int ni = 0; ni < 4; ni++) {
            const int cc = warp_n * 32 + ni * 8 + tig * 2;
            if (FULL || cc < nvalid) {
                mxa = fmaxf(mxa, c[mi][ni][0]);
                mxb = fmaxf(mxb, c[mi][ni][2]);
            }
            if (FULL || cc + 1 < nvalid) {
                mxa = fmaxf(mxa, c[mi][ni][1]);
                mxb = fmaxf(mxb, c[mi][ni][3]);
            }
        }
        mxa = fmaxf(mxa, __shfl_xor_sync(0xffffffffu, mxa, 1));
        mxa = fmaxf(mxa, __shfl_xor_sync(0xffffffffu, mxa, 2));
        mxb = fmaxf(mxb, __shfl_xor_sync(0xffffffffu, mxb, 1));
        mxb = fmaxf(mxb, __shfl_xor_sync(0xffffffffu, mxb, 2));
#pragma unroll
        for (int ni = 0; ni < 4; ni++) {
            const int cc = warp_n * 32 + ni * 8 + tig * 2;
            if (FULL || cc < nvalid)     { sa += __expf(c[mi][ni][0] - mxa);
                                           sb += __expf(c[mi][ni][2] - mxb); }
            if (FULL || cc + 1 < nvalid) { sa += __expf(c[mi][ni][1] - mxa);
                                           sb += __expf(c[mi][ni][3] - mxb); }
        }
        sa += __shfl_xor_sync(0xffffffffu, sa, 1);
        sa += __shfl_xor_sync(0xffffffffu, sa, 2);
        sb += __shfl_xor_sync(0xffffffffu, sb, 1);
        sb += __shfl_xor_sync(0xffffffffu, sb, 2);
        if (tig == 0) {
            g_part2[((size_t)r0 * NT_ + nt) * 4 + warp_n]       = make_float2(mxa, sa);
            g_part2[((size_t)(r0 + 8) * NT_ + nt) * 4 + warp_n] = make_float2(mxb, sb);
        }
    }
}

template<bool WRITE>
__global__ void __launch_bounds__(256, 1)
gemm_pass(float* __restrict__ out) {
    extern __shared__ char smc[];
    const uint32_t sbase = smem_u32(smc);
    float* Cs = reinterpret_cast<float*>(smc + SM_C);

    const int tid = threadIdx.x;
    const int wid = tid >> 5, lane = tid & 31;
    const int warp_m = wid & 1, warp_n = wid >> 1;   // 2(m) x 4(n)
    const int qid = lane >> 2, tig = lane & 3;
    const int m0 = blockIdx.y * 128;

    auto issueB = [&](int nt, int buf) {
        if (nt < NT_) {
            const int n0 = nt * 128;
            const uint32_t d0 = sbase + SM_B0 + (buf << 15);
#pragma unroll
            for (int f = tid; f < 2048; f += 256) {
                int row = f >> 4, c8 = f & 15;
                uint32_t dst = d0 + swz(row, c8);
                const char* src = reinterpret_cast<const char*>(g_negh)
                                + (size_t)(n0 + row) * 256 + c8 * 16;
                asm volatile("cp.async.cg.shared.global [%0], [%1], 16;"
                             :: "r"(dst), "l"(src) : "memory");
            }
        }
        asm volatile("cp.async.commit_group;" ::: "memory");
    };

    issueB(blockIdx.x, 0);
    issueB(blockIdx.x + GX_, 1);

    // ---- stage A tile (g_yh m-block) into swizzled smem ----
#pragma unroll
    for (int f = tid; f < 2048; f += 256) {
        int row = f >> 4, c8 = f & 15;
        uint4 v = *reinterpret_cast<const uint4*>(g_yh + (m0 + row) * E_ + c8 * 8);
        *reinterpret_cast<uint4*>(smc + SM_A + swz(row, c8)) = v;
    }

    int idx = 0;
    for (int nt = blockIdx.x; nt < NT_; nt += GX_, idx++) {
        asm volatile("cp.async.wait_group 1;" ::: "memory");
        __syncthreads();   // buffer idx%3 visible to all; also protects Cs reuse

        const uint32_t aB = sbase + SM_A;
        const int bsel = idx - (idx / 3) * 3;
        const uint32_t bB = sbase + SM_B0 + (bsel << 15);

        float c[4][4][4];
#pragma unroll
        for (int mi = 0; mi < 4; mi++)
#pragma unroll
            for (int ni = 0; ni < 4; ni++)
#pragma unroll
                for (int j = 0; j < 4; j++) c[mi][ni][j] = 0.f;

#pragma unroll
        for (int ks = 0; ks < 8; ks++) {
            const int c8a = ks * 2 + (lane >> 4);
            uint32_t a[4][4], b[4][2];
#pragma unroll
            for (int mi = 0; mi < 4; mi++) {
                int row = warp_m * 64 + mi * 16 + (lane & 15);
                uint32_t addr = aB + swz(row, c8a);
                asm volatile("ldmatrix.sync.aligned.m8n8.x4.shared.b16 "
                             "{%0,%1,%2,%3}, [%4];"
                             : "=r"(a[mi][0]), "=r"(a[mi][1]),
                               "=r"(a[mi][2]), "=r"(a[mi][3]) : "r"(addr));
            }
#pragma unroll
            for (int j = 0; j < 2; j++) {
                const int g = lane >> 3;
                int ni_x = 2 * j + (g >> 1);
                int half = g & 1;
                int nrow = warp_n * 32 + ni_x * 8 + (lane & 7);
                uint32_t addr = bB + swz(nrow, ks * 2 + half);
                asm volatile("ldmatrix.sync.aligned.m8n8.x4.shared.b16 "
                             "{%0,%1,%2,%3}, [%4];"
                             : "=r"(b[2 * j][0]), "=r"(b[2 * j][1]),
                               "=r"(b[2 * j + 1][0]), "=r"(b[2 * j + 1][1])
                             : "r"(addr));
            }
#pragma unroll
            for (int mi = 0; mi < 4; mi++)
#pragma unroll
                for (int ni = 0; ni < 4; ni++)
                    asm volatile(
                        "mma.sync.aligned.m16n8k16.row.col.f32.f16.f16.f32 "
                        "{%0,%1,%2,%3},{%4,%5,%6,%7},{%8,%9},{%0,%1,%2,%3};"
                        : "+f"(c[mi][ni][0]), "+f"(c[mi][ni][1]),
                          "+f"(c[mi][ni][2]), "+f"(c[mi][ni][3])
                        : "r"(a[mi][0]), "r"(a[mi][1]), "r"(a[mi][2]), "r"(a[mi][3]),
                          "r"(b[ni][0]), "r"(b[ni][1]));
        }

        // buffer (bsel+2)%3 was fully consumed in iteration idx-1 (all warps
        // passed this iteration's loop-top barrier) -> safe without a barrier.
        issueB(nt + 2 * GX_, (bsel + 2 >= 3) ? bsel - 1 : bsel + 2);

        const int n0 = nt * 128;
        const int nvalid = min(128, V_ - n0);

        if (!WRITE) {
            if (nvalid == 128) partials<true >(c, nvalid, m0, n0, warp_m, warp_n, qid, tig, nt);
            else               partials<false>(c, nvalid, m0, n0, warp_m, warp_n, qid, tig, nt);
        } else {
            // ---- stage C into smem ----
#pragma unroll
            for (int mi = 0; mi < 4; mi++) {
                const int r0 = warp_m * 64 + mi * 16 + qid;
                float* c0p = Cs + r0 * CPAD + warp_n * 32 + tig * 2;
#pragma unroll
                for (int ni = 0; ni < 4; ni++) {
                    *reinterpret_cast<float2*>(c0p + ni * 8) =
                        make_float2(c[mi][ni][0], c[mi][ni][1]);
                    *reinterpret_cast<float2*>(c0p + ni * 8 + 8 * CPAD) =
                        make_float2(c[mi][ni][2], c[mi][ni][3]);
                }
            }
            __syncthreads();

            // ---- coalesced copy with lse subtraction ----
            if (nvalid == 128) {
#pragma unroll
                for (int j = 0; j < 16; j++) {
                    const int row = (wid << 4) + j;
                    const float ls = g_lse[m0 + row];
                    const float* cs = Cs + row * CPAD;
                    float* ob = out + (size_t)(m0 + row) * V_ + n0;
                    if (!(row & 1)) {
#pragma unroll
                        for (int k = 0; k < 2; k++) {
                            int col = ((k << 5) + lane) << 1;
                            *reinterpret_cast<float2*>(ob + col) =
                                make_float2(cs[col] - ls, cs[col + 1] - ls);
                        }
                    } else {
                        if (lane == 0)  ob[0]   = cs[0]   - ls;
                        if (lane == 31) ob[127] = cs[127] - ls;
#pragma unroll
                        for (int k = 0; k < 2; k++) {
                            int i2 = (k << 5) + lane;
                            if (i2 < 63) {
                                int col = 1 + (i2 << 1);
                                *reinterpret_cast<float2*>(ob + col) =
                                    make_float2(cs[col] - ls, cs[col + 1] - ls);
                            }
                        }
                    }
                }
            } else {
                for (int j = 0; j < 16; j++) {
                    const int row = (wid << 4) + j;
                    const float ls = g_lse[m0 + row];
                    const float* cs = Cs + row * CPAD;
                    float* ob = out + (size_t)(m0 + row) * V_ + n0;
                    for (int col = lane; col < nvalid; col += 32)
                        ob[col] = cs[col] - ls;
                }
            }
        }
    }
}

// ---------------- K4: combine partials -> lse[b] ----------------------------
__global__ void lse_kernel() {
    const int b = blockIdx.x, t = threadIdx.x;   // 128 threads
    __shared__ float sm_[128], sl[128];
    const int NP = NT_ * 4;
    float m = -INFINITY, l = 0.f;
    for (int i = t; i < NP; i += 128) {
        float2 p = g_part2[(size_t)b * NP + i];
        float nm = fmaxf(m, p.x);
        l = l * expf(m - nm) + p.y * expf(p.x - nm);
        m = nm;
    }
    sm_[t] = m; sl[t] = l;
    __syncthreads();
    for (int s = 64; s > 0; s >>= 1) {
        if (t < s) {
            float m2 = sm_[t + s], l2 = sl[t + s];
            float nm = fmaxf(sm_[t], m2);
            sl[t] = sl[t] * expf(sm_[t] - nm) + l2 * expf(m2 - nm);
            sm_[t] = nm;
        }
        __syncthreads();
    }
    if (t == 0) g_lse[b] = sm_[0] + logf(sl[0]);
}

extern "C" void kernel_launch(void* const* d_in, const int* in_sizes, int n_in,
                              void* d_out, int out_size) {
    const float* xs     = (const float*)d_in[0];
    const float* metric = (const float*)d_in[1];
    const float* EMB    = (const float*)d_in[2];
    const float* NEG    = (const float*)d_in[3];
    float* out = (float*)d_out;

    prep_kernel<<<3072, 256>>>((const float4*)NEG, (const float4*)xs);
    embed_metric_kernel<<<B_, 128>>>(EMB, metric);

    cudaFuncSetAttribute(gemm_pass<false>,
                         cudaFuncAttributeMaxDynamicSharedMemorySize, SMEM_BYTES);
    cudaFuncSetAttribute(gemm_pass<true>,
                         cudaFuncAttributeMaxDynamicSharedMemorySize, SMEM_BYTES);

    gemm_pass<false><<<dim3(GX_, 8), 256, SMEM_BYTES>>>(out);
    lse_kernel<<<B_, 128>>>();
    gemm_pass<true ><<<dim3(GX_, 8), 256, SMEM_BYTES>>>(out);
}